// round 5
// baseline (speedup 1.0000x reference)
#include <cuda_runtime.h>
#include <cstdint>

// ---------------------------------------------------------------------------
//   NF=4, NLOC=2048, NNEI=64, EMBED=128, PAIR_DIM=64, H=8, HD=16
//   force[f,l,c] = sum_n delta[n,c] * sum_h probs[h,n] * sv[nlist[n],h]
//   sv[j,h] = qn[j].Wvf[h],  Wvf[h,e] = sum_d Wforce[h*16+d]*Wv[h*16+d,e]
//   bias[h,n] = rstd_n*(Wg[h].pair[n] - mean_n*S[h]) + C[h]
// ---------------------------------------------------------------------------

#define NROWS 8192
#define EMB   128
#define NNEI  64
#define NH    8

__device__ __align__(16) float g_q[NROWS * EMB];
__device__ __align__(16) float g_k[NROWS * EMB];
__device__ __align__(16) float g_sv[NROWS * NH];
__device__ __align__(16) float g_wvf[NH * EMB];
__device__ __align__(16) float g_wg[NH * 64];
__device__ float g_S[NH];
__device__ float g_C[NH];

// ---- packed fp32x2 helpers (SASS FFMA2 path, PTX-only) --------------------
__device__ __forceinline__ unsigned long long pk2(float x, float y) {
    unsigned long long r;
    asm("mov.b64 %0, {%1, %2};" : "=l"(r) : "f"(x), "f"(y));
    return r;
}
__device__ __forceinline__ void upk2(unsigned long long v, float& x, float& y) {
    asm("mov.b64 {%0, %1}, %2;" : "=f"(x), "=f"(y) : "l"(v));
}
__device__ __forceinline__ void fma2(unsigned long long& acc,
                                     unsigned long long a, unsigned long long b) {
    asm("fma.rn.f32x2 %0, %1, %2, %0;" : "+l"(acc) : "l"(a), "l"(b));
}

// ---------------------------------------------------------------------------
// Prep: blocks 0..7 -> Wvf row h; block 8 -> Wg, S, C
// ---------------------------------------------------------------------------
__global__ void prep_kernel(const float* __restrict__ Wv,
                            const float* __restrict__ Wf,
                            const float* __restrict__ Wbias,
                            const float* __restrict__ bbias,
                            const float* __restrict__ pn_g,
                            const float* __restrict__ pn_b)
{
    const int t = threadIdx.x, b = blockIdx.x;
    if (b < 8) {
        if (t < 128) {
            float acc = 0.f;
#pragma unroll
            for (int d = 0; d < 16; d++)
                acc += Wf[b * 16 + d] * Wv[(b * 16 + d) * EMB + t];
            g_wvf[b * EMB + t] = acc;
        }
    } else {
        __shared__ float wg_sh[512], cb_sh[512];
#pragma unroll
        for (int rep = 0; rep < 2; rep++) {
            int j = t + 256 * rep;
            float wb = Wbias[j];
            int p = j & 63;
            float wg = wb * pn_g[p];
            g_wg[j]  = wg;
            wg_sh[j] = wg;
            cb_sh[j] = wb * pn_b[p];
        }
        __syncthreads();
        int w = t >> 5, l = t & 31;
        float s = wg_sh[w * 64 + l] + wg_sh[w * 64 + 32 + l];
        float c = cb_sh[w * 64 + l] + cb_sh[w * 64 + 32 + l];
#pragma unroll
        for (int o = 16; o; o >>= 1) {
            s += __shfl_xor_sync(0xffffffffu, s, o);
            c += __shfl_xor_sync(0xffffffffu, c, o);
        }
        if (l == 0) { g_S[w] = s; g_C[w] = c + bbias[w]; }
    }
}

// ---------------------------------------------------------------------------
// Kernel A: LN(query) + Q/K GEMMs + sv (unchanged — known correct)
// ---------------------------------------------------------------------------
#define AROWS 32
__global__ __launch_bounds__(256) void lnqk_kernel(
    const float* __restrict__ query,
    const float* __restrict__ ln_g, const float* __restrict__ ln_b,
    const float* __restrict__ Wq,  const float* __restrict__ Wk)
{
    __shared__ float qn_s[AROWS][132];
    __shared__ float Ws[128][17];

    const int t = threadIdx.x, w = t >> 5, l = t & 31;
    const int row0 = blockIdx.x * AROWS;
    const int m = blockIdx.y;

#pragma unroll
    for (int i = 0; i < 4; i++) {
        int r = w * 4 + i;
        float4 x = reinterpret_cast<const float4*>(query + (size_t)(row0 + r) * EMB)[l];
        float s = x.x + x.y + x.z + x.w;
#pragma unroll
        for (int o = 16; o; o >>= 1) s += __shfl_xor_sync(0xffffffffu, s, o);
        float mean = s * (1.f / 128.f);
        float d0 = x.x - mean, d1 = x.y - mean, d2 = x.z - mean, d3 = x.w - mean;
        float vs = d0 * d0 + d1 * d1 + d2 * d2 + d3 * d3;
#pragma unroll
        for (int o = 16; o; o >>= 1) vs += __shfl_xor_sync(0xffffffffu, vs, o);
        float inv = rsqrtf(vs * (1.f / 128.f) + 1e-5f);
        int e = 4 * l;
        qn_s[r][e + 0] = d0 * inv * ln_g[e + 0] + ln_b[e + 0];
        qn_s[r][e + 1] = d1 * inv * ln_g[e + 1] + ln_b[e + 1];
        qn_s[r][e + 2] = d2 * inv * ln_g[e + 2] + ln_b[e + 2];
        qn_s[r][e + 3] = d3 * inv * ln_g[e + 3] + ln_b[e + 3];
    }
    __syncthreads();

    const float* W  = (m == 0) ? Wq : Wk;
    float* outp     = (m == 0) ? g_q : g_k;
    const int o     = t & 127;
    const int rbase = (t >> 7) * 16;

    float acc[16];
#pragma unroll
    for (int r = 0; r < 16; r++) acc[r] = 0.f;

    for (int ec = 0; ec < 8; ec++) {
#pragma unroll
        for (int i = 0; i < 8; i++) {
            int flat = t + 256 * i;
            int oo = flat >> 4, ee = flat & 15;
            Ws[oo][ee] = W[oo * EMB + ec * 16 + ee];
        }
        __syncthreads();
        float wreg[16];
#pragma unroll
        for (int e = 0; e < 16; e++) wreg[e] = Ws[o][e];
#pragma unroll
        for (int r = 0; r < 16; r++) {
            const float4* qp = reinterpret_cast<const float4*>(&qn_s[rbase + r][ec * 16]);
#pragma unroll
            for (int v = 0; v < 4; v++) {
                float4 a = qp[v];
                acc[r] += a.x * wreg[4 * v] + a.y * wreg[4 * v + 1]
                        + a.z * wreg[4 * v + 2] + a.w * wreg[4 * v + 3];
            }
        }
        __syncthreads();
    }
    const float scale = (m == 0) ? 0.25f : 1.f;
#pragma unroll
    for (int r = 0; r < 16; r++)
        outp[(size_t)(row0 + rbase + r) * EMB + o] = acc[r] * scale;

    if (m == 0) {
        int h = t & 7, r = t >> 3;
        const float4* qp = reinterpret_cast<const float4*>(&qn_s[r][0]);
        const float4* wp = reinterpret_cast<const float4*>(&g_wvf[h * EMB]);
        float a2 = 0.f;
#pragma unroll
        for (int v = 0; v < 32; v++) {
            float4 a = qp[v], bb = wp[v];
            a2 += a.x * bb.x + a.y * bb.y + a.z * bb.z + a.w * bb.w;
        }
        g_sv[(size_t)(row0 + r) * NH + h] = a2;
    }
}

// ---------------------------------------------------------------------------
// Kernel B (restructured): pair in registers, no staging syncs before gather,
// f32x2 bias GEMV, mask folded into softmax. smem ~2.6 KB.
// ---------------------------------------------------------------------------
__global__ __launch_bounds__(256) void attn_force_kernel(
    const float* __restrict__ pair,  const int* __restrict__ nlist,
    const float* __restrict__ delta, const float* __restrict__ mask,
    float* __restrict__ out)
{
    const int fl = blockIdx.x;
    const int f  = fl >> 11;
    const int lrow = fl & 2047;
    const int t = threadIdx.x, w = t >> 5, l = t & 31;

    __shared__ float logit[8][65];     // q.k, then +bias, then probs
    __shared__ float Wg_s[8][64];
    __shared__ float S_s[8], C_s[8];
    __shared__ float t_s[64];

    // ---- issue all independent loads up front (max MLP) ----
    const int n  = w * 8 + (l >> 2);   // this thread's pair row
    const int qd = l & 3;              // quarter of the 64 pair dims

    const float4* pr = reinterpret_cast<const float4*>(
        pair + (size_t)fl * 4096 + n * 64 + qd * 16);
    float4 a0 = pr[0], a1 = pr[1], a2 = pr[2], a3 = pr[3];

    // per-warp nlist (lanes 0..7 hold the 8 indices this warp gathers)
    int nq = nlist[(size_t)fl * NNEI + w * 8 + (l & 7)];

    // q quad for this lane (warp-coalesced, L1-cached across warps)
    float4 qv = reinterpret_cast<const float4*>(g_q + (size_t)fl * EMB)[l];

    // mask values for softmax phase (warp w == head w)
    const float* mrow = mask + (((size_t)(f * NH + w)) * 2048 + lrow) * NNEI;
    float mk0 = mrow[l], mk1 = mrow[l + 32];

    // delta values for force phase
    float dl0 = 0.f, dl1 = 0.f;
    if (w < 3) {
        const float* dp = delta + (size_t)fl * NNEI * 3;
        dl0 = dp[l * 3 + w];
        dl1 = dp[(l + 32) * 3 + w];
    }

    // stage Wg / S / C
    reinterpret_cast<float*>(Wg_s)[t]       = g_wg[t];
    reinterpret_cast<float*>(Wg_s)[t + 256] = g_wg[t + 256];
    if (t < 8) { S_s[t] = g_S[t]; C_s[t] = g_C[t]; }

    // ---- P1: k-gather + q.k (warp-local, no block sync needed) ----
    {
        const float* kbase = g_k + (size_t)f * 2048 * EMB;
#pragma unroll
        for (int i = 0; i < 8; i++) {
            int nid = __shfl_sync(0xffffffffu, nq, i);
            float4 kx = reinterpret_cast<const float4*>(kbase + (size_t)nid * EMB)[l];
            float s = qv.x * kx.x + qv.y * kx.y + qv.z * kx.z + qv.w * kx.w;
            s += __shfl_xor_sync(0xffffffffu, s, 1);
            s += __shfl_xor_sync(0xffffffffu, s, 2);
            if ((l & 3) == 0) logit[l >> 2][w * 8 + i] = s;
        }
    }
    __syncthreads();   // Wg_s ready + all q.k logits visible

    // ---- P2: pair-row stats from registers ----
    unsigned long long pa[8];
    pa[0] = pk2(a0.x, a0.y); pa[1] = pk2(a0.z, a0.w);
    pa[2] = pk2(a1.x, a1.y); pa[3] = pk2(a1.z, a1.w);
    pa[4] = pk2(a2.x, a2.y); pa[5] = pk2(a2.z, a2.w);
    pa[6] = pk2(a3.x, a3.y); pa[7] = pk2(a3.z, a3.w);

    float s1 = a0.x + a0.y + a0.z + a0.w + a1.x + a1.y + a1.z + a1.w
             + a2.x + a2.y + a2.z + a2.w + a3.x + a3.y + a3.z + a3.w;
    unsigned long long s2p = 0ull;
#pragma unroll
    for (int j = 0; j < 8; j++) fma2(s2p, pa[j], pa[j]);
    float s2lo, s2hi; upk2(s2p, s2lo, s2hi);
    float s2 = s2lo + s2hi;
    s1 += __shfl_xor_sync(0xffffffffu, s1, 1);
    s1 += __shfl_xor_sync(0xffffffffu, s1, 2);
    s2 += __shfl_xor_sync(0xffffffffu, s2, 1);
    s2 += __shfl_xor_sync(0xffffffffu, s2, 2);
    float mean = s1 * (1.f / 64.f);
    float rstd = rsqrtf(s2 * (1.f / 64.f) - mean * mean + 1e-5f);
    float mr = mean * rstd;

    // ---- P3: folded bias, 8 heads, f32x2 dot over this thread's 16 dims ----
#pragma unroll
    for (int h = 0; h < 8; h++) {
        const unsigned long long* wp = reinterpret_cast<const unsigned long long*>(
            &Wg_s[h][qd * 16]);
        unsigned long long acc = 0ull;
#pragma unroll
        for (int j = 0; j < 8; j++) fma2(acc, pa[j], wp[j]);
        float dlo, dhi; upk2(acc, dlo, dhi);
        float d = dlo + dhi;
        d += __shfl_xor_sync(0xffffffffu, d, 1);
        d += __shfl_xor_sync(0xffffffffu, d, 2);
        if ((h & 3) == qd)
            logit[h][n] += rstd * d - mr * S_s[h] + C_s[h];
    }
    __syncthreads();

    // ---- P4: softmax per head (warp w == head), mask folded in ----
    {
        float v0 = logit[w][l] + mk0, v1 = logit[w][l + 32] + mk1;
        float mx = fmaxf(v0, v1);
#pragma unroll
        for (int o = 16; o; o >>= 1) mx = fmaxf(mx, __shfl_xor_sync(0xffffffffu, mx, o));
        float e0 = __expf(v0 - mx), e1 = __expf(v1 - mx);
        float ssum = e0 + e1;
#pragma unroll
        for (int o = 16; o; o >>= 1) ssum += __shfl_xor_sync(0xffffffffu, ssum, o);
        float inv = __fdividef(1.f, ssum);
        logit[w][l]      = e0 * inv;
        logit[w][l + 32] = e1 * inv;
    }
    __syncthreads();

    // ---- P5: t[n] = sum_h probs[h][n] * sv[nlist[n],h] ----
    if (t < 64) {
        int nid = nlist[(size_t)fl * NNEI + t];       // L1/L2 hit
        const float4* sp = reinterpret_cast<const float4*>(
            g_sv + ((size_t)f * 2048 + nid) * NH);
        float4 sa = sp[0], sb = sp[1];
        float acc = logit[0][t] * sa.x + logit[1][t] * sa.y
                  + logit[2][t] * sa.z + logit[3][t] * sa.w
                  + logit[4][t] * sb.x + logit[5][t] * sb.y
                  + logit[6][t] * sb.z + logit[7][t] * sb.w;
        t_s[t] = acc;
    }
    __syncthreads();

    // ---- P6: force[c] = sum_n delta[n][c] * t[n] ----
    if (w < 3) {
        float acc = dl0 * t_s[l] + dl1 * t_s[l + 32];
#pragma unroll
        for (int o = 16; o; o >>= 1) acc += __shfl_xor_sync(0xffffffffu, acc, o);
        if (l == 0) out[fl * 3 + w] = acc;
    }
}

// ---------------------------------------------------------------------------
extern "C" void kernel_launch(void* const* d_in, const int* in_sizes, int n_in,
                              void* d_out, int out_size)
{
    const float* query  = (const float*)d_in[0];
    const float* pair   = (const float*)d_in[1];
    const int*   nlist  = (const int*)d_in[2];
    const float* delta  = (const float*)d_in[3];
    const float* mask   = (const float*)d_in[4];
    const float* ln_g   = (const float*)d_in[5];
    const float* ln_b   = (const float*)d_in[6];
    const float* pn_g   = (const float*)d_in[7];
    const float* pn_b   = (const float*)d_in[8];
    const float* Wq     = (const float*)d_in[9];
    const float* Wk     = (const float*)d_in[10];
    const float* Wv     = (const float*)d_in[11];
    const float* Wbias  = (const float*)d_in[12];
    const float* bbias  = (const float*)d_in[13];
    const float* Wforce = (const float*)d_in[14];
    float* out = (float*)d_out;

    prep_kernel<<<9, 256>>>(Wv, Wforce, Wbias, bbias, pn_g, pn_b);
    lnqk_kernel<<<dim3(NROWS / AROWS, 2), 256>>>(query, ln_g, ln_b, Wq, Wk);
    attn_force_kernel<<<NROWS, 256>>>(pair, nlist, delta, mask, out);
}

// round 6
// speedup vs baseline: 1.3699x; 1.3699x over previous
#include <cuda_runtime.h>
#include <cstdint>

// ---------------------------------------------------------------------------
//   NF=4, NLOC=2048, NNEI=64, EMBED=128, PAIR_DIM=64, H=8, HD=16
//   force[f,l,c] = sum_n delta[n,c] * sum_h probs[h,n] * sv[nlist[n],h]
//   sv[j,h] = qn[j].Wvf[h],  Wvf[h,e] = sum_d Wforce[h*16+d]*Wv[h*16+d,e]
//   bias[h,n] = rstd_n*(Wg[h].pair[n] - mean_n*S[h]) + C[h]
// ---------------------------------------------------------------------------

#define NROWS 8192
#define EMB   128
#define NNEI  64
#define NH    8

__device__ __align__(16) float g_q[NROWS * EMB];
__device__ __align__(16) float g_k[NROWS * EMB];
__device__ __align__(16) float g_sv[NROWS * NH];
__device__ __align__(16) float g_wg[NH * 64];
__device__ float g_S[NH];
__device__ float g_C[NH];

// ---- packed fp32x2 helpers (SASS FFMA2, PTX-only) --------------------------
__device__ __forceinline__ void upk2(unsigned long long v, float& x, float& y) {
    asm("mov.b64 {%0, %1}, %2;" : "=f"(x), "=f"(y) : "l"(v));
}
__device__ __forceinline__ void fma2(unsigned long long& acc,
                                     unsigned long long a, unsigned long long b) {
    asm("fma.rn.f32x2 %0, %1, %2, %0;" : "+l"(acc) : "l"(a), "l"(b));
}

// ---------------------------------------------------------------------------
// Kernel A: LN(query) + Q/K GEMMs (f32x2) + sv; absorbs old prep work.
//   m==0 blocks: compute Wvf into smem for sv;  block (0,0): Wg/S/C.
// ---------------------------------------------------------------------------
#define AROWS 32
__global__ __launch_bounds__(256) void lnqk_kernel(
    const float* __restrict__ query,
    const float* __restrict__ ln_g, const float* __restrict__ ln_b,
    const float* __restrict__ Wq,  const float* __restrict__ Wk,
    const float* __restrict__ Wv,  const float* __restrict__ Wf,
    const float* __restrict__ Wbias, const float* __restrict__ bbias,
    const float* __restrict__ pn_g,  const float* __restrict__ pn_b)
{
    __shared__ float qn_s[AROWS][132];
    __shared__ float Ws[128][18];      // 18: 8B-aligned rows for LDS.64
    __shared__ float wvf_s[8][132];

    const int t = threadIdx.x, w = t >> 5, l = t & 31;
    const int row0 = blockIdx.x * AROWS;
    const int m = blockIdx.y;

    // ---- LayerNorm: warp w -> rows w*4..w*4+3, lane holds 4 elems ----
#pragma unroll
    for (int i = 0; i < 4; i++) {
        int r = w * 4 + i;
        float4 x = reinterpret_cast<const float4*>(query + (size_t)(row0 + r) * EMB)[l];
        float s = x.x + x.y + x.z + x.w;
#pragma unroll
        for (int o = 16; o; o >>= 1) s += __shfl_xor_sync(0xffffffffu, s, o);
        float mean = s * (1.f / 128.f);
        float d0 = x.x - mean, d1 = x.y - mean, d2 = x.z - mean, d3 = x.w - mean;
        float vs = d0 * d0 + d1 * d1 + d2 * d2 + d3 * d3;
#pragma unroll
        for (int o = 16; o; o >>= 1) vs += __shfl_xor_sync(0xffffffffu, vs, o);
        float inv = rsqrtf(vs * (1.f / 128.f) + 1e-5f);
        int e = 4 * l;
        qn_s[r][e + 0] = d0 * inv * ln_g[e + 0] + ln_b[e + 0];
        qn_s[r][e + 1] = d1 * inv * ln_g[e + 1] + ln_b[e + 1];
        qn_s[r][e + 2] = d2 * inv * ln_g[e + 2] + ln_b[e + 2];
        qn_s[r][e + 3] = d3 * inv * ln_g[e + 3] + ln_b[e + 3];
    }

    // ---- absorbed prep work (no extra sync: covered by the one below) ----
    if (m == 0) {
#pragma unroll
        for (int i = 0; i < 4; i++) {
            int j = t + 256 * i;               // 1024 wvf entries
            int h = j >> 7, e = j & 127;
            float acc = 0.f;
#pragma unroll
            for (int d = 0; d < 16; d++)
                acc += Wf[h * 16 + d] * Wv[(h * 16 + d) * EMB + e];
            wvf_s[h][e] = acc;
        }
        if (blockIdx.x == 0) {
#pragma unroll
            for (int rep = 0; rep < 2; rep++) {
                int j = t + 256 * rep;
                g_wg[j] = Wbias[j] * pn_g[j & 63];
            }
            if (t < 8) {
                float s = 0.f, c = 0.f;
#pragma unroll
                for (int p = 0; p < 64; p++) {
                    float wb = Wbias[t * 64 + p];
                    s += wb * pn_g[p];
                    c += wb * pn_b[p];
                }
                g_S[t] = s;
                g_C[t] = c + bbias[t];
            }
        }
    }
    __syncthreads();

    const float* W  = (m == 0) ? Wq : Wk;
    float* outp     = (m == 0) ? g_q : g_k;
    const int o     = t & 127;
    const int rbase = (t >> 7) * 16;

    unsigned long long acc2[16];
#pragma unroll
    for (int r = 0; r < 16; r++) acc2[r] = 0ull;

    for (int ec = 0; ec < 8; ec++) {
#pragma unroll
        for (int i = 0; i < 8; i++) {
            int flat = t + 256 * i;
            int oo = flat >> 4, ee = flat & 15;
            Ws[oo][ee] = W[oo * EMB + ec * 16 + ee];
        }
        __syncthreads();
        unsigned long long wp2[8];
        const unsigned long long* wrow =
            reinterpret_cast<const unsigned long long*>(&Ws[o][0]);
#pragma unroll
        for (int j = 0; j < 8; j++) wp2[j] = wrow[j];
#pragma unroll
        for (int r = 0; r < 16; r++) {
            const unsigned long long* qp2 =
                reinterpret_cast<const unsigned long long*>(&qn_s[rbase + r][ec * 16]);
#pragma unroll
            for (int j = 0; j < 8; j++) fma2(acc2[r], qp2[j], wp2[j]);
        }
        __syncthreads();
    }
    const float scale = (m == 0) ? 0.25f : 1.f;
#pragma unroll
    for (int r = 0; r < 16; r++) {
        float lo, hi; upk2(acc2[r], lo, hi);
        outp[(size_t)(row0 + rbase + r) * EMB + o] = (lo + hi) * scale;
    }

    if (m == 0) {   // sv = qn @ Wvf^T
        int h = t & 7, r = t >> 3;
        const float4* qp = reinterpret_cast<const float4*>(&qn_s[r][0]);
        const float4* wp = reinterpret_cast<const float4*>(&wvf_s[h][0]);
        float a2 = 0.f;
#pragma unroll
        for (int v = 0; v < 32; v++) {
            float4 a = qp[v], bb = wp[v];
            a2 += a.x * bb.x + a.y * bb.y + a.z * bb.z + a.w * bb.w;
        }
        g_sv[(size_t)(row0 + r) * NH + h] = a2;
    }
}

// ---------------------------------------------------------------------------
// Kernel B: exact R4 structure (known 127.5 µs): smem-staged pair tile,
// gather-k attn logits, folded pair-LN bias, softmax, force.
// ---------------------------------------------------------------------------
__global__ __launch_bounds__(256) void attn_force_kernel(
    const float* __restrict__ pair,  const int* __restrict__ nlist,
    const float* __restrict__ delta, const float* __restrict__ mask,
    float* __restrict__ out)
{
    const int fl = blockIdx.x;
    const int f  = fl >> 11;
    const int lrow = fl & 2047;
    const int t = threadIdx.x, w = t >> 5, l = t & 31;

    __shared__ float q_s[128];
    __shared__ int   nidx[64];
    __shared__ float pn_s[64][68];
    __shared__ float Wg_s[8][64];
    __shared__ float logit[8][65];
    __shared__ float sv_s[64][9];
    __shared__ float mean_s[64], rstd_s[64];
    __shared__ float S_s[8], C_s[8];
    __shared__ float t_s[64];

    if (t < 128) q_s[t] = g_q[(size_t)fl * EMB + t];
    if (t < 64)  nidx[t] = nlist[(size_t)fl * NNEI + t];
    {
        const float4* psrc = reinterpret_cast<const float4*>(pair) + (size_t)fl * 1024;
#pragma unroll
        for (int r = 0; r < 4; r++) {
            int idx = t + 256 * r;
            int n = idx >> 4, c = idx & 15;
            *reinterpret_cast<float4*>(&pn_s[n][4 * c]) = psrc[idx];
        }
    }
    reinterpret_cast<float*>(Wg_s)[t]       = g_wg[t];
    reinterpret_cast<float*>(Wg_s)[t + 256] = g_wg[t + 256];
    if (t < 8) { S_s[t] = g_S[t]; C_s[t] = g_C[t]; }
    __syncthreads();

    // ---- P1: k-gather + q.k ----
    {
        const float q0 = q_s[4 * l], q1 = q_s[4 * l + 1],
                    q2 = q_s[4 * l + 2], q3 = q_s[4 * l + 3];
        const float* kbase = g_k + (size_t)f * 2048 * EMB;
#pragma unroll
        for (int i = 0; i < 8; i++) {
            int n = w * 8 + i;
            float4 kx = reinterpret_cast<const float4*>(kbase + (size_t)nidx[n] * EMB)[l];
            float s = q0 * kx.x + q1 * kx.y + q2 * kx.z + q3 * kx.w;
            s += __shfl_xor_sync(0xffffffffu, s, 1);
            s += __shfl_xor_sync(0xffffffffu, s, 2);
            if ((l & 3) == 0) logit[l >> 2][n] = s;
        }
    }
    // ---- sv gather ----
    if (t < 128) {
        int n = t >> 1, half = t & 1;
        float4 s4 = reinterpret_cast<const float4*>(
            g_sv + ((size_t)f * 2048 + nidx[n]) * NH)[half];
        sv_s[n][half * 4 + 0] = s4.x;
        sv_s[n][half * 4 + 1] = s4.y;
        sv_s[n][half * 4 + 2] = s4.z;
        sv_s[n][half * 4 + 3] = s4.w;
    }
    // ---- P2: pair row stats (4 lanes per row) ----
    {
        int n = t >> 2, qd = t & 3;
        const float4* pr = reinterpret_cast<const float4*>(&pn_s[n][0]);
        float s = 0.f, s2 = 0.f;
#pragma unroll
        for (int v = 0; v < 4; v++) {
            float4 a = pr[qd * 4 + v];
            s  += a.x + a.y + a.z + a.w;
            s2 += a.x * a.x + a.y * a.y + a.z * a.z + a.w * a.w;
        }
        s  += __shfl_xor_sync(0xffffffffu, s, 1);
        s  += __shfl_xor_sync(0xffffffffu, s, 2);
        s2 += __shfl_xor_sync(0xffffffffu, s2, 1);
        s2 += __shfl_xor_sync(0xffffffffu, s2, 2);
        if (qd == 0) {
            float mean = s * (1.f / 64.f);
            mean_s[n] = mean;
            rstd_s[n] = rsqrtf(s2 * (1.f / 64.f) - mean * mean + 1e-5f);
        }
    }
    __syncthreads();

    // ---- P3: folded bias (2 heads per thread, Wg broadcast) ----
    {
        int n = t & 63, hg = t >> 6;
        int h0 = 2 * hg, h1 = h0 + 1;
        float mean = mean_s[n], rstd = rstd_s[n];
        float d0 = 0.f, d1 = 0.f;
        const float4* pr = reinterpret_cast<const float4*>(&pn_s[n][0]);
        const float4* w0 = reinterpret_cast<const float4*>(&Wg_s[h0][0]);
        const float4* w1 = reinterpret_cast<const float4*>(&Wg_s[h1][0]);
#pragma unroll
        for (int v = 0; v < 16; v++) {
            float4 a = pr[v], b0 = w0[v], b1 = w1[v];
            d0 += a.x * b0.x + a.y * b0.y + a.z * b0.z + a.w * b0.w;
            d1 += a.x * b1.x + a.y * b1.y + a.z * b1.z + a.w * b1.w;
        }
        float m0 = mask[(((size_t)(f * NH + h0)) * 2048 + lrow) * NNEI + n];
        float m1 = mask[(((size_t)(f * NH + h1)) * 2048 + lrow) * NNEI + n];
        logit[h0][n] += rstd * (d0 - mean * S_s[h0]) + C_s[h0] + m0;
        logit[h1][n] += rstd * (d1 - mean * S_s[h1]) + C_s[h1] + m1;
    }
    __syncthreads();

    // ---- P4: softmax (warp w == head) ----
    {
        float v0 = logit[w][l], v1 = logit[w][l + 32];
        float mx = fmaxf(v0, v1);
#pragma unroll
        for (int o = 16; o; o >>= 1) mx = fmaxf(mx, __shfl_xor_sync(0xffffffffu, mx, o));
        float e0 = __expf(v0 - mx), e1 = __expf(v1 - mx);
        float ssum = e0 + e1;
#pragma unroll
        for (int o = 16; o; o >>= 1) ssum += __shfl_xor_sync(0xffffffffu, ssum, o);
        float inv = __fdividef(1.f, ssum);
        logit[w][l]      = e0 * inv;
        logit[w][l + 32] = e1 * inv;
    }
    __syncthreads();

    // ---- P5: t[n] = sum_h probs[h][n]*sv[n][h] ----
    if (t < 64) {
        float acc = 0.f;
#pragma unroll
        for (int h = 0; h < 8; h++) acc += logit[h][t] * sv_s[t][h];
        t_s[t] = acc;
    }
    __syncthreads();

    // ---- P6: force ----
    if (w < 3) {
        const float* dp = delta + (size_t)fl * NNEI * 3;
        float acc = dp[l * 3 + w] * t_s[l] + dp[(l + 32) * 3 + w] * t_s[l + 32];
#pragma unroll
        for (int o = 16; o; o >>= 1) acc += __shfl_xor_sync(0xffffffffu, acc, o);
        if (l == 0) out[fl * 3 + w] = acc;
    }
}

// ---------------------------------------------------------------------------
extern "C" void kernel_launch(void* const* d_in, const int* in_sizes, int n_in,
                              void* d_out, int out_size)
{
    const float* query  = (const float*)d_in[0];
    const float* pair   = (const float*)d_in[1];
    const int*   nlist  = (const int*)d_in[2];
    const float* delta  = (const float*)d_in[3];
    const float* mask   = (const float*)d_in[4];
    const float* ln_g   = (const float*)d_in[5];
    const float* ln_b   = (const float*)d_in[6];
    const float* pn_g   = (const float*)d_in[7];
    const float* pn_b   = (const float*)d_in[8];
    const float* Wq     = (const float*)d_in[9];
    const float* Wk     = (const float*)d_in[10];
    const float* Wv     = (const float*)d_in[11];
    const float* Wbias  = (const float*)d_in[12];
    const float* bbias  = (const float*)d_in[13];
    const float* Wforce = (const float*)d_in[14];
    float* out = (float*)d_out;

    lnqk_kernel<<<dim3(NROWS / AROWS, 2), 256>>>(query, ln_g, ln_b, Wq, Wk,
                                                 Wv, Wforce, Wbias, bbias,
                                                 pn_g, pn_b);
    attn_force_kernel<<<NROWS, 256>>>(pair, nlist, delta, mask, out);
}